// round 16
// baseline (speedup 1.0000x reference)
#include <cuda_runtime.h>
#include <cuda_bf16.h>

// Furthest-point sampling — round 16: coords ride the tagged slots; all
// warps poll. Base: round-15 (2777us, tagged-slot exchange proven).
//
// Slot = 32 bytes (one L2 sector), two SELF-TAGGED 16B halves:
//   half A: {tag = i+1, dist_bits, ~idx, x_bits}
//   half B: {tag = i+1, y_bits, z_bits, 0}
// A half is accepted only when its own tag matches, so the two-STG.128
// visibility race is harmless. Winner coords come straight out of the
// poll-reduce -> the dependent g_xyz[widx] L2 fetch is GONE (and the pack
// kernel with it). All 8 warps poll + tuple-reduce redundantly -> the
// winner never crosses shared memory: second __syncthreads + broadcast GONE.
//
// One __syncthreads per iteration is sufficient for the s_red WAR hazard:
// no warp can pass poll(i) before its own block's warp0 published slot(i),
// which happens only after warp0 read s_red(i).
//
// Parity double-buffering (proven): a block publishes iter i+2 into parity p
// only after its poll(i+1) passed, which needs every block's publish(i+1),
// which follows their poll(i) reads of parity p. Tags strictly increase;
// init kernel re-zeros slots each graph replay.
//
// Output stored as FLOAT32 (round-9 root cause: validator reads d_out as f32).
//
// Math (validated EXACT, rel_err = 0.0 in rounds 9/10/12/13/15):
//   dists: __fadd_rn/__fmul_rn, left-to-right ((dx^2+dy^2)+dz^2), fminf.
//   key = (dist_bits<<32) | (0xFFFFFFFF - idx); dist >= 0 keeps float bits
//   order-preserving; complemented idx => max() prefers the SMALLEST index
//   on exact ties (jnp.argmax first-occurrence); thread-local scan ascends.

#define NBLK  64
#define NTHR  256
#define NWARP (NTHR / 32)
#define PPT   25     // 64*256*25 = 409600 >= 400000

__device__ uint4 g_slot[2][NBLK][2];   // [parity][block][half]

__global__ void fps_init_kernel() {
    int t = threadIdx.x;
    if (t < 2 * NBLK * 2)
        ((uint4*)g_slot)[t] = make_uint4(0u, 0u, 0u, 0u);
}

__global__ __launch_bounds__(NTHR, 1)
void fps_coop_kernel(const float* __restrict__ feats, int n, int m,
                     float* __restrict__ out)
{
    const int tid  = threadIdx.x;
    const int bid  = blockIdx.x;
    const int gtid = bid * NTHR + tid;
    const int lane = tid & 31;
    const int warp = tid >> 5;
    const int stride = NBLK * NTHR;      // 16384

    // Register-resident point state (25 points/thread)
    float px[PPT], py[PPT], pz[PPT], dist[PPT];
#pragma unroll
    for (int k = 0; k < PPT; ++k) {
        int g = gtid + k * stride;
        if (g < n) {
            // feats row = 64 floats (256B); first 16B aligned -> one LDG.128
            float4 v = *reinterpret_cast<const float4*>(feats + (size_t)g * 64);
            px[k] = v.x; py[k] = v.y; pz[k] = v.z;
        } else {
            px[k] = 0.f; py[k] = 0.f; pz[k] = 0.f;
        }
        dist[k] = 1e10f;
    }

    float qx = feats[0], qy = feats[1], qz = feats[2];   // seed = index 0
    if (gtid == 0) out[0] = 0.0f;

    __shared__ unsigned long long s_redK[NWARP];
    __shared__ float4 s_redC[NWARP];

    for (int i = 0; i < m - 1; ++i) {
        // ---- 1) min-dist update + thread-local best (ascending: first max) ----
        float bestd = -1.0f, bx = 0.f, by = 0.f, bz = 0.f;
        int   besti = 0;
#pragma unroll
        for (int k = 0; k < PPT; ++k) {
            int g = gtid + k * stride;
            float dx = __fadd_rn(px[k], -qx);
            float dy = __fadd_rn(py[k], -qy);
            float dz = __fadd_rn(pz[k], -qz);
            float d  = __fadd_rn(__fadd_rn(__fmul_rn(dx, dx),
                                           __fmul_rn(dy, dy)),
                                 __fmul_rn(dz, dz));
            float nd = fminf(dist[k], d);
            dist[k] = nd;
            if (g < n && nd > bestd) {
                bestd = nd; besti = g;
                bx = px[k]; by = py[k]; bz = pz[k];
            }
        }
        unsigned long long key =
            ((unsigned long long)__float_as_uint(bestd) << 32) |
            (unsigned long long)(0xFFFFFFFFu - (unsigned)besti);

        // ---- 2) warp tuple argmax (key + coords) ----
#pragma unroll
        for (int off = 16; off > 0; off >>= 1) {
            unsigned long long ok = __shfl_down_sync(0xFFFFFFFFu, key, off);
            float ox = __shfl_down_sync(0xFFFFFFFFu, bx, off);
            float oy = __shfl_down_sync(0xFFFFFFFFu, by, off);
            float oz = __shfl_down_sync(0xFFFFFFFFu, bz, off);
            if (ok > key) { key = ok; bx = ox; by = oy; bz = oz; }
        }
        if (lane == 0) {
            s_redK[warp] = key;
            s_redC[warp] = make_float4(bx, by, bz, 0.f);
        }
        __syncthreads();   // the ONLY block barrier per iteration

        // ---- 3) warp0: block tuple reduce + publish tagged 32B slot ----
        const unsigned want = (unsigned)(i + 1);
        const int par = i & 1;
        if (warp == 0) {
            unsigned long long bk = (lane < NWARP) ? s_redK[lane] : 0ull;
            float4 bc = (lane < NWARP) ? s_redC[lane]
                                       : make_float4(0.f, 0.f, 0.f, 0.f);
#pragma unroll
            for (int off = 4; off > 0; off >>= 1) {
                unsigned long long ok = __shfl_down_sync(0xFFFFFFFFu, bk, off);
                float ox = __shfl_down_sync(0xFFFFFFFFu, bc.x, off);
                float oy = __shfl_down_sync(0xFFFFFFFFu, bc.y, off);
                float oz = __shfl_down_sync(0xFFFFFFFFu, bc.z, off);
                if (ok > bk) { bk = ok; bc.x = ox; bc.y = oy; bc.z = oz; }
            }
            if (lane == 0) {
                uint4 a = make_uint4(want, (unsigned)(bk >> 32),
                                     (unsigned)(bk & 0xFFFFFFFFull),
                                     __float_as_uint(bc.x));
                uint4 b = make_uint4(want, __float_as_uint(bc.y),
                                     __float_as_uint(bc.z), 0u);
                __stcg(&g_slot[par][bid][0], a);
                __stcg(&g_slot[par][bid][1], b);
            }
        }

        // ---- 4) EVERY warp polls all 64 slots (2 per lane, 2 halves) ----
        unsigned long long k0 = 0ull, k1 = 0ull;
        float3 c0 = make_float3(0.f, 0.f, 0.f);
        float3 c1 = make_float3(0.f, 0.f, 0.f);
        bool d0 = false, d1 = false;
        for (;;) {
            if (!d0) {
                uint4 a = __ldcv(&g_slot[par][lane][0]);
                uint4 b = __ldcv(&g_slot[par][lane][1]);
                if (a.x == want && b.x == want) {
                    k0 = ((unsigned long long)a.y << 32) | a.z;
                    c0 = make_float3(__uint_as_float(a.w),
                                     __uint_as_float(b.y),
                                     __uint_as_float(b.z));
                    d0 = true;
                }
            }
            if (!d1) {
                uint4 a = __ldcv(&g_slot[par][lane + 32][0]);
                uint4 b = __ldcv(&g_slot[par][lane + 32][1]);
                if (a.x == want && b.x == want) {
                    k1 = ((unsigned long long)a.y << 32) | a.z;
                    c1 = make_float3(__uint_as_float(a.w),
                                     __uint_as_float(b.y),
                                     __uint_as_float(b.z));
                    d1 = true;
                }
            }
            if (__all_sync(0xFFFFFFFFu, d0 && d1)) break;
        }

        // ---- 5) per-warp grid tuple argmax over the 64 partials ----
        unsigned long long bk;
        float3 bc;
        if (k0 > k1) { bk = k0; bc = c0; } else { bk = k1; bc = c1; }
#pragma unroll
        for (int off = 16; off > 0; off >>= 1) {
            unsigned long long ok = __shfl_xor_sync(0xFFFFFFFFu, bk, off);
            float ox = __shfl_xor_sync(0xFFFFFFFFu, bc.x, off);
            float oy = __shfl_xor_sync(0xFFFFFFFFu, bc.y, off);
            float oz = __shfl_xor_sync(0xFFFFFFFFu, bc.z, off);
            if (ok > bk) { bk = ok; bc.x = ox; bc.y = oy; bc.z = oz; }
        }
        // xor-reduce: every lane of every warp now holds the global winner.
        qx = bc.x; qy = bc.y; qz = bc.z;

        if (bid == 0 && tid == 0)
            out[i + 1] =
                (float)(0xFFFFFFFFu - (unsigned int)(bk & 0xFFFFFFFFull));
        // WAR safety: s_redK/s_redC for iter i+1 are written only after this
        // iteration's poll passes in the writing warp, and warp0 read them
        // before publishing slot(i), which every poll(i) requires. The next
        // __syncthreads then orders warp0's read vs everyone's next write.
    }
}

extern "C" void kernel_launch(void* const* d_in, const int* in_sizes, int n_in,
                              void* d_out, int out_size) {
    const float* feats = (const float*)d_in[0];
    float* out = (float*)d_out;
    int n = in_sizes[0] / 64;   // WIDTH = 64 -> N = 400000
    int m = out_size;           // 1000

    fps_init_kernel<<<1, 256>>>();

    void* args[4] = { (void*)&feats, (void*)&n, (void*)&m, (void*)&out };
    cudaLaunchCooperativeKernel((void*)fps_coop_kernel,
                                dim3(NBLK), dim3(NTHR), args, 0, (cudaStream_t)0);
}

// round 17
// speedup vs baseline: 1.9949x; 1.9949x over previous
#include <cuda_runtime.h>
#include <cuda_bf16.h>

// Furthest-point sampling — round 17: round-15 skeleton (2777us, proven) +
// coords-in-slot from round 16, MINUS round 16's regression cause.
//
// Round-16 post-mortem: letting all 8 warps/block poll multiplied slot-poll
// L2 traffic 8x (issue 8.6->17.9%, L2 0.4->1.6%) and contended the very LTS
// slices the producers commit through -> 3837us. Lesson: exactly ONE polling
// warp per block.
//
// This build: warp0-only poll (R15), smem winner broadcast (R15), but the
// slot is 32B = two SELF-TAGGED 16B halves carrying the winner's coords:
//   half A: {tag = i+1, dist_bits, ~idx, x_bits}
//   half B: {tag = i+1, y_bits, z_bits, 0}
// A half is accepted only when its own tag matches (two-store visibility
// race harmless). Winner coords come out of the poll-reduce directly ->
// the dependent g_xyz[widx] L2 fetch (~400cyc) is gone, pack kernel gone.
//
// Parity double-buffering (proven): a block publishes iter i+2 into parity p
// only after its poll(i+1) passed, which needs every block's publish(i+1),
// which follows their poll(i) reads of parity p. Tags strictly increase;
// init kernel re-zeros slots each graph replay.
//
// Output stored as FLOAT32 (round-9 root cause: validator reads d_out as f32).
//
// Math (validated EXACT, rel_err = 0.0 in rounds 9/10/12/13/15/16):
//   dists: __fadd_rn/__fmul_rn, left-to-right ((dx^2+dy^2)+dz^2), fminf.
//   key = (dist_bits<<32) | (0xFFFFFFFF - idx); dist >= 0 keeps float bits
//   order-preserving; complemented idx => max() prefers the SMALLEST index
//   on exact ties (jnp.argmax first-occurrence); thread-local scan ascends.

#define NBLK  64
#define NTHR  256
#define NWARP (NTHR / 32)
#define PPT   25     // 64*256*25 = 409600 >= 400000

__device__ uint4 g_slot[2][NBLK][2];   // [parity][block][half]

__global__ void fps_init_kernel() {
    int t = threadIdx.x;
    if (t < 2 * NBLK * 2)
        ((uint4*)g_slot)[t] = make_uint4(0u, 0u, 0u, 0u);
}

__global__ __launch_bounds__(NTHR, 1)
void fps_coop_kernel(const float* __restrict__ feats, int n, int m,
                     float* __restrict__ out)
{
    const int tid  = threadIdx.x;
    const int bid  = blockIdx.x;
    const int gtid = bid * NTHR + tid;
    const int lane = tid & 31;
    const int warp = tid >> 5;
    const int stride = NBLK * NTHR;      // 16384

    // Register-resident point state (25 points/thread)
    float px[PPT], py[PPT], pz[PPT], dist[PPT];
#pragma unroll
    for (int k = 0; k < PPT; ++k) {
        int g = gtid + k * stride;
        if (g < n) {
            // feats row = 64 floats (256B); first 16B aligned -> one LDG.128
            float4 v = *reinterpret_cast<const float4*>(feats + (size_t)g * 64);
            px[k] = v.x; py[k] = v.y; pz[k] = v.z;
        } else {
            px[k] = 0.f; py[k] = 0.f; pz[k] = 0.f;
        }
        dist[k] = 1e10f;
    }

    float qx = feats[0], qy = feats[1], qz = feats[2];   // seed = index 0
    if (gtid == 0) out[0] = 0.0f;

    __shared__ unsigned long long s_redK[NWARP];
    __shared__ float4 s_redC[NWARP];
    __shared__ float s_q[4];             // x, y, z, widx-as-float

    for (int i = 0; i < m - 1; ++i) {
        // ---- 1) min-dist update + thread-local best (ascending: first max) ----
        float bestd = -1.0f, bx = 0.f, by = 0.f, bz = 0.f;
        int   besti = 0;
#pragma unroll
        for (int k = 0; k < PPT; ++k) {
            int g = gtid + k * stride;
            float dx = __fadd_rn(px[k], -qx);
            float dy = __fadd_rn(py[k], -qy);
            float dz = __fadd_rn(pz[k], -qz);
            float d  = __fadd_rn(__fadd_rn(__fmul_rn(dx, dx),
                                           __fmul_rn(dy, dy)),
                                 __fmul_rn(dz, dz));
            float nd = fminf(dist[k], d);
            dist[k] = nd;
            if (g < n && nd > bestd) {
                bestd = nd; besti = g;
                bx = px[k]; by = py[k]; bz = pz[k];
            }
        }
        unsigned long long key =
            ((unsigned long long)__float_as_uint(bestd) << 32) |
            (unsigned long long)(0xFFFFFFFFu - (unsigned)besti);

        // ---- 2) warp tuple argmax (key + coords) ----
#pragma unroll
        for (int off = 16; off > 0; off >>= 1) {
            unsigned long long ok = __shfl_down_sync(0xFFFFFFFFu, key, off);
            float ox = __shfl_down_sync(0xFFFFFFFFu, bx, off);
            float oy = __shfl_down_sync(0xFFFFFFFFu, by, off);
            float oz = __shfl_down_sync(0xFFFFFFFFu, bz, off);
            if (ok > key) { key = ok; bx = ox; by = oy; bz = oz; }
        }
        if (lane == 0) {
            s_redK[warp] = key;
            s_redC[warp] = make_float4(bx, by, bz, 0.f);
        }
        __syncthreads();

        const unsigned want = (unsigned)(i + 1);
        const int par = i & 1;

        if (warp == 0) {
            // ---- 3) block tuple reduce (8 warps) + publish tagged slot ----
            unsigned long long bk = (lane < NWARP) ? s_redK[lane] : 0ull;
            float4 bc = (lane < NWARP) ? s_redC[lane]
                                       : make_float4(0.f, 0.f, 0.f, 0.f);
#pragma unroll
            for (int off = 4; off > 0; off >>= 1) {
                unsigned long long ok = __shfl_down_sync(0xFFFFFFFFu, bk, off);
                float ox = __shfl_down_sync(0xFFFFFFFFu, bc.x, off);
                float oy = __shfl_down_sync(0xFFFFFFFFu, bc.y, off);
                float oz = __shfl_down_sync(0xFFFFFFFFu, bc.z, off);
                if (ok > bk) { bk = ok; bc.x = ox; bc.y = oy; bc.z = oz; }
            }
            if (lane == 0) {
                uint4 a = make_uint4(want, (unsigned)(bk >> 32),
                                     (unsigned)(bk & 0xFFFFFFFFull),
                                     __float_as_uint(bc.x));
                uint4 b = make_uint4(want, __float_as_uint(bc.y),
                                     __float_as_uint(bc.z), 0u);
                __stcg(&g_slot[par][bid][0], a);
                __stcg(&g_slot[par][bid][1], b);
            }

            // ---- 4) warp0 ONLY: poll all 64 slots (2 per lane) ----
            unsigned long long k0 = 0ull, k1 = 0ull;
            float3 c0 = make_float3(0.f, 0.f, 0.f);
            float3 c1 = make_float3(0.f, 0.f, 0.f);
            bool d0 = false, d1 = false;
            for (;;) {
                if (!d0) {
                    uint4 a = __ldcv(&g_slot[par][lane][0]);
                    uint4 b = __ldcv(&g_slot[par][lane][1]);
                    if (a.x == want && b.x == want) {
                        k0 = ((unsigned long long)a.y << 32) | a.z;
                        c0 = make_float3(__uint_as_float(a.w),
                                         __uint_as_float(b.y),
                                         __uint_as_float(b.z));
                        d0 = true;
                    }
                }
                if (!d1) {
                    uint4 a = __ldcv(&g_slot[par][lane + 32][0]);
                    uint4 b = __ldcv(&g_slot[par][lane + 32][1]);
                    if (a.x == want && b.x == want) {
                        k1 = ((unsigned long long)a.y << 32) | a.z;
                        c1 = make_float3(__uint_as_float(a.w),
                                         __uint_as_float(b.y),
                                         __uint_as_float(b.z));
                        d1 = true;
                    }
                }
                if (__all_sync(0xFFFFFFFFu, d0 && d1)) break;
            }

            // ---- 5) grid tuple argmax over the 64 partials ----
            float3 bc3;
            if (k0 > k1) { bk = k0; bc3 = c0; } else { bk = k1; bc3 = c1; }
#pragma unroll
            for (int off = 16; off > 0; off >>= 1) {
                unsigned long long ok = __shfl_down_sync(0xFFFFFFFFu, bk, off);
                float ox = __shfl_down_sync(0xFFFFFFFFu, bc3.x, off);
                float oy = __shfl_down_sync(0xFFFFFFFFu, bc3.y, off);
                float oz = __shfl_down_sync(0xFFFFFFFFu, bc3.z, off);
                if (ok > bk) { bk = ok; bc3.x = ox; bc3.y = oy; bc3.z = oz; }
            }
            if (lane == 0) {
                s_q[0] = bc3.x; s_q[1] = bc3.y; s_q[2] = bc3.z;
                s_q[3] = (float)(0xFFFFFFFFu -
                                 (unsigned int)(bk & 0xFFFFFFFFull));
            }
        }
        __syncthreads();

        // ---- 6) broadcast winner; store index AS FLOAT ----
        qx = s_q[0]; qy = s_q[1]; qz = s_q[2];
        if (bid == 0 && tid == 0) out[i + 1] = s_q[3];
        // WAR safety: s_red*/s_q rewritten only after all threads pass this
        // iteration's two __syncthreads; slot parity analyzed in header.
    }
}

extern "C" void kernel_launch(void* const* d_in, const int* in_sizes, int n_in,
                              void* d_out, int out_size) {
    const float* feats = (const float*)d_in[0];
    float* out = (float*)d_out;
    int n = in_sizes[0] / 64;   // WIDTH = 64 -> N = 400000
    int m = out_size;           // 1000

    fps_init_kernel<<<1, 256>>>();

    void* args[4] = { (void*)&feats, (void*)&n, (void*)&m, (void*)&out };
    cudaLaunchCooperativeKernel((void*)fps_coop_kernel,
                                dim3(NBLK), dim3(NTHR), args, 0, (cudaStream_t)0);
}